// round 15
// baseline (speedup 1.0000x reference)
#include <cuda_runtime.h>

// Problem dims (fixed by the dataset)
#define BB 8
#define CC 19
#define HH 512
#define WW 1024
#define HWW (HH*WW)
#define NPIX (BB*HWW)

#define TS 64   // UF tile 64x64

// flag-in-parent encoding (global)
#define FLAGB 0x40000000
#define IDXM  0x3FFFFFFF
// local (shared sp) flag
#define LOCF  0x40000000
#define LIDXM 0x3FFFFFFF

// seam slot counts (64-tiles: 7 h-seams, 15 v-seams per image)
#define NSEAM_H (BB * 7 * WW)           // 57344
#define NSEAM_V (BB * 15 * HH)          // 61440
#define NSEAM   (NSEAM_H + NSEAM_V)

#define NLL_GRID (NPIX / 4 / 256)       // 4096 blocks

// ---------------- scratch (device globals; no allocation allowed) ----------
__device__ int            g_parent[NPIX];
__device__ unsigned char  g_wmask[NPIX];   // bit0=weak, bit1=strong
__device__ double         g_sum_nll;
__device__ double         g_sum_bnll;
__device__ unsigned long long g_cnt_valid;
__device__ unsigned long long g_cnt_b;
__device__ unsigned int   g_done = 0;

// ================= shared-memory union-find helpers ========================
// masked find: safe before and after flag-marking (flags live only on roots)
__device__ __forceinline__ int find_s(int* sp, int x) {
    int p = sp[x] & LIDXM;
    while (p != x) {
        int gp = sp[p] & LIDXM;
        if (gp != p) sp[x] = gp;
        x = p; p = gp;
    }
    return x;
}

__device__ __forceinline__ void union_s(int* sp, int a, int b) {
    while (true) {
        a = find_s(sp, a);
        b = find_s(sp, b);
        if (a == b) return;
        if (a < b) { int t = a; a = b; b = t; }
        int old = atomicCAS(&sp[a], a, b);   // pre-mark: roots unflagged
        if (old == a) return;
        a = old & LIDXM;
    }
}

// ============ fused Sobel + NMS + threshold + tile-local UF + flags ========
// 64x64 tile, 256 threads, 16 px/thread; integer sobel in 16-bit smem
__global__ __launch_bounds__(256) void k_canny(const int* __restrict__ tgt) {
    __shared__ short          simg[TS + 4][TS + 5];  // 68x69 shorts
    __shared__ unsigned short smag[TS + 2][TS + 3];  // 66x67 ushorts
    __shared__ int            sp[TS * TS];
    __shared__ unsigned char  lw[TS * TS];

    const int tid = threadIdx.x;
    const int b  = blockIdx.z;
    const int h0 = blockIdx.y * TS;
    const int w0 = blockIdx.x * TS;
    const int* timg = tgt + b * HWW;
    const int base = b * HWW;

    // zero the accumulators once (k_canny completes before any reader runs)
    if (blockIdx.x == 0 && blockIdx.y == 0 && blockIdx.z == 0 && tid == 0) {
        g_sum_nll = 0.0; g_sum_bnll = 0.0; g_cnt_valid = 0ULL; g_cnt_b = 0ULL;
    }

    // ---- image load: val = (target*255)&255 -------------------------------
    // interior 64x64 via int4, no clamps (tiles align with image)
#pragma unroll
    for (int i = 0; i < 4; i++) {
        int q = tid + 256 * i;            // int4 id 0..1023
        int row = q >> 4;                 // 16 int4 per row
        int col = (q & 15) * 4;
        int4 v = __ldg((const int4*)(timg + (h0 + row) * WW + w0 + col));
        simg[2 + row][2 + col + 0] = (short)((v.x * 255) & 255);
        simg[2 + row][2 + col + 1] = (short)((v.y * 255) & 255);
        simg[2 + row][2 + col + 2] = (short)((v.z * 255) & 255);
        simg[2 + row][2 + col + 3] = (short)((v.w * 255) & 255);
    }
    // halo rows: rr in {0,1,66,67}, cc 0..67 (272 cells)
    for (int l = tid; l < 4 * (TS + 4); l += 256) {
        int r4 = l / (TS + 4), cc = l - r4 * (TS + 4);
        int rrs = (r4 < 2) ? r4 : r4 + TS;
        int gh = min(max(h0 - 2 + rrs, 0), HH - 1);
        int gw = min(max(w0 - 2 + cc, 0), WW - 1);
        int t = __ldg(timg + gh * WW + gw);
        simg[rrs][cc] = (short)((t * 255) & 255);
    }
    // halo cols: rr 2..65, cc in {0,1,66,67} (256 cells, exactly 1/thread)
    {
        int c4 = tid & 3;
        int ccs = (c4 < 2) ? c4 : c4 + TS;
        int r2 = tid >> 2;                // 0..63
        int gh = h0 + r2;                 // in-bounds
        int gw = min(max(w0 - 2 + ccs, 0), WW - 1);
        int t = __ldg(timg + gh * WW + gw);
        simg[2 + r2][ccs] = (short)((t * 255) & 255);
    }
    __syncthreads();

    // ---- center mags: 4 groups of 4 px, separable int sobel ---------------
    unsigned int secpack = 0;   // 2 bits per pixel, idx = (p*2+g)*4+k
#pragma unroll
    for (int p = 0; p < 2; p++) {
#pragma unroll
        for (int g = 0; g < 2; g++) {
            int lr  = (tid >> 3) + 32 * p;
            int lcb = (tid & 7) * 8 + 4 * g;
            int r0[6], r1[6], r2[6];
#pragma unroll
            for (int j = 0; j < 6; j++) {
                r0[j] = simg[lr + 1][lcb + 1 + j];
                r1[j] = simg[lr + 2][lcb + 1 + j];
                r2[j] = simg[lr + 3][lcb + 1 + j];
            }
            int v[6], d[6];
#pragma unroll
            for (int j = 0; j < 6; j++) {
                v[j] = r0[j] + 2 * r1[j] + r2[j];
                d[j] = r2[j] - r0[j];
            }
#pragma unroll
            for (int k = 0; k < 4; k++) {
                int gx = v[k + 2] - v[k];
                int gy = d[k] + 2 * d[k + 1] + d[k + 2];
                int ax = abs(gx), ay = abs(gy);
                float axf = (float)ax, ayf = (float)ay;
                unsigned int sec;
                if (ayf <= axf * 0.41421356f)      sec = 0;
                else if (ayf >= axf * 2.41421356f) sec = 1;
                else sec = (gx * gy >= 0) ? 2 : 3;
                smag[lr + 1][lcb + 1 + k] = (unsigned short)(ax + ay);
                secpack |= sec << (2 * ((p * 2 + g) * 4 + k));
            }
        }
    }
    // ---- halo ring of smag: 260 cells -------------------------------------
    if (tid < 260) {
        int mr, mc;
        if (tid < 132) {                  // rows 0 and 65, cols 0..65
            mr = (tid < 66) ? 0 : 65;
            mc = (tid < 66) ? tid : tid - 66;
        } else {                          // cols 0 and 65, rows 1..64
            int t2 = tid - 132;
            mc = (t2 < 64) ? 0 : 65;
            mr = 1 + (t2 & 63);
        }
        int gh = h0 + mr - 1, gw = w0 + mc - 1;
        int m = 0;
        if (gh >= 0 && gh < HH && gw >= 0 && gw < WW) {
            int a00 = simg[mr][mc],     a01 = simg[mr][mc+1],     a02 = simg[mr][mc+2];
            int a10 = simg[mr+1][mc],                             a12 = simg[mr+1][mc+2];
            int a20 = simg[mr+2][mc],   a21 = simg[mr+2][mc+1],   a22 = simg[mr+2][mc+2];
            int gx = (a02 + 2*a12 + a22) - (a00 + 2*a10 + a20);
            int gy = (a20 + 2*a21 + a22) - (a00 + 2*a01 + a02);
            m = abs(gx) + abs(gy);
        }
        smag[mr][mc] = (unsigned short)m;
    }
    __syncthreads();

    // ---- NMS + thresholds; write wmask; init sp/lw ------------------------
#pragma unroll
    for (int p = 0; p < 2; p++) {
#pragma unroll
        for (int g = 0; g < 2; g++) {
            int lr  = (tid >> 3) + 32 * p;
            int lcb = (tid & 7) * 8 + 4 * g;
            int mr = lr + 1;
            uchar4 mout;
            unsigned char* mo = (unsigned char*)&mout;
#pragma unroll
            for (int k = 0; k < 4; k++) {
                int mc = lcb + 1 + k;
                int mag = smag[mr][mc];
                int sec = (secpack >> (2 * ((p * 2 + g) * 4 + k))) & 3;
                int dr = (sec == 0) ? 0 : -1;
                int dc = (sec == 1) ? 0 : ((sec == 3) ? 1 : -1);
                int n1 = smag[mr + dr][mc + dc];
                int n2 = smag[mr - dr][mc - dc];
                bool keep = (mag >= n1) && (mag > n2);
                unsigned char m = 0;
                if (keep && mag > 50)  m |= 1;
                if (keep && mag > 150) m |= 2;
                int l = lr * TS + lcb + k;
                mo[k] = m;
                lw[l] = m;
                if (m & 1) sp[l] = l;   // sp touched only at weak entries
            }
            int gidx = base + (h0 + lr) * WW + w0 + lcb;
            *(uchar4*)(g_wmask + gidx) = mout;
        }
    }
    __syncthreads();

    // ---- local UF over weak pixels ----------------------------------------
#pragma unroll
    for (int k = 0; k < 16; k++) {
        int l = tid * 16 + k;
        if (!(lw[l] & 1)) continue;
        int cc = l & (TS - 1);
        if (cc > 0 && (lw[l - 1] & 1)) union_s(sp, l, l - 1);
        if (l >= TS) {
            if (lw[l - TS] & 1)                    union_s(sp, l, l - TS);
            if (cc > 0      && (lw[l - TS - 1] & 1)) union_s(sp, l, l - TS - 1);
            if (cc < TS - 1 && (lw[l - TS + 1] & 1)) union_s(sp, l, l - TS + 1);
        }
    }
    __syncthreads();

    // ---- mark roots of strong-containing components (flag bit in sp) ------
#pragma unroll
    for (int k = 0; k < 16; k++) {
        int l = tid * 16 + k;
        if (lw[l] & 2) {
            int root = find_s(sp, l);
            atomicOr(&sp[root], LOCF);
        }
    }
    __syncthreads();

    // ---- write global parents; roots carry strong-flag in bit 30 ----------
#pragma unroll
    for (int k = 0; k < 16; k++) {
        int l = tid * 16 + k;
        if (!(lw[l] & 1)) continue;
        int root = find_s(sp, l);
        int rr = l >> 6, cc = l & (TS - 1);
        int rtr = root >> 6, rtc = root & (TS - 1);
        int groot = base + (h0 + rtr) * WW + (w0 + rtc);
        int gi    = base + (h0 + rr) * WW + (w0 + cc);
        int val = (l == root && (sp[root] & LOCF)) ? (groot | FLAGB) : groot;
        g_parent[gi] = val;
    }
}

// ============ global union-find with flag propagation ======================
__device__ __forceinline__ int uf_find(int* P, int x) {
    int p = P[x] & IDXM;
    while (p != x) {
        int gp = P[p] & IDXM;
        if (gp != p) P[x] = gp;   // halving: x is non-root, pointer-only entry
        x = p; p = gp;
    }
    return x;
}

__device__ __forceinline__ void uf_setflag(int* P, int x) {
    while (true) {
        int r = uf_find(P, x);
        int old = atomicOr(&P[r], FLAGB);
        if ((old & IDXM) == r) return;   // landed on a root: done
        x = old & IDXM;                  // r was re-linked concurrently: chase
    }
}

__device__ __forceinline__ void uf_union(int* P, int a, int b) {
    while (true) {
        a = uf_find(P, a);
        b = uf_find(P, b);
        if (a == b) return;
        if (a < b) { int t = a; a = b; b = t; }
        int aval = P[a];
        if ((aval & IDXM) != a) continue;        // stale root, retry
        int old = atomicCAS(&P[a], aval, b);     // full-word compare: flag-safe
        if (old == aval) {
            if (aval & FLAGB) uf_setflag(P, b);  // carry flag to the new root
            return;
        }
    }
}

// ====== seam-direct cross-tile unions (64-granularity) =====================
__global__ __launch_bounds__(256) void k_seam() {
    int t = blockIdx.x * blockDim.x + threadIdx.x;
    if (t >= NSEAM) return;

    if (t < NSEAM_H) {
        // horizontal seams: rows h = 64,...,448 (7 per image), w fastest
        int b  = t / (7 * WW);
        int r  = t - b * (7 * WW);
        int hi = r / WW;
        int w  = r - hi * WW;
        int h  = (hi + 1) * TS;
        int base = b * HWW;
        int i = base + h * WW + w;
        if (!(g_wmask[i] & 1)) return;
        int rowup = base + (h - 1) * WW;
        if (g_wmask[rowup + w] & 1)                     uf_union(g_parent, i, rowup + w);
        if (w > 0      && (g_wmask[rowup + w - 1] & 1)) uf_union(g_parent, i, rowup + w - 1);
        if (w < WW - 1 && (g_wmask[rowup + w + 1] & 1)) uf_union(g_parent, i, rowup + w + 1);
    } else {
        // vertical seams: cols w = 64,...,960 (15 per image), wi FASTEST
        int t2 = t - NSEAM_H;
        int wi = t2 % 15;
        int r  = t2 / 15;
        int h  = r % HH;
        int b  = r / HH;
        int w  = (wi + 1) * TS;
        int base = b * HWW;
        int i = base + h * WW + w;       // pixel with lc==0
        bool iw  = (g_wmask[i] & 1) != 0;
        bool lw_ = (g_wmask[i - 1] & 1) != 0;
        if (iw && lw_) uf_union(g_parent, i, i - 1);
        if ((h & (TS - 1)) != 0) {
            int up = i - WW;
            if (iw  && (g_wmask[up - 1] & 1)) uf_union(g_parent, i, up - 1);
            if (lw_ && (g_wmask[up] & 1))     uf_union(g_parent, i - 1, up);
        }
    }
}

// ====== fused NLL + boundary reduce + final (chunked-5: best measured) =====
__global__ __launch_bounds__(256, 4) void k_nllfused(const float* __restrict__ in,
                                                     const int* __restrict__ tgt,
                                                     float* __restrict__ out) {
    const int tid = threadIdx.x;
    int p0 = (blockIdx.x * 256 + tid) * 4;
    int b = p0 / HWW;
    int off = p0 - b * HWW;
    const float* basep = in + (size_t)b * (CC * HWW) + off;

    int4 t4 = *(const int4*)(tgt + p0);
    int tg[4] = {t4.x, t4.y, t4.z, t4.w};

    float s[4]  = {0.f, 0.f, 0.f, 0.f};
    float xt[4] = {0.f, 0.f, 0.f, 0.f};

#pragma unroll 1
    for (int c0 = 0; c0 < CC; c0 += 5) {
        const int CN = (CC - c0 < 5) ? (CC - c0) : 5;
        float f[5][4];
#pragma unroll
        for (int j = 0; j < 5; j++) {
            if (j < CN) {
                float4 v = __ldg((const float4*)(basep + (size_t)(c0 + j) * HWW));
                f[j][0] = v.x; f[j][1] = v.y; f[j][2] = v.z; f[j][3] = v.w;
            }
        }
#pragma unroll
        for (int j = 0; j < 5; j++) {
            if (j < CN) {
#pragma unroll
                for (int k = 0; k < 4; k++) {
                    s[k] += __expf(f[j][k]);
                    if (c0 + j == tg[k]) xt[k] = f[j][k];
                }
            }
        }
    }

    uchar4 m4 = *(const uchar4*)(g_wmask + p0);
    unsigned char mm[4] = {m4.x, m4.y, m4.z, m4.w};

    double v1 = 0.0, v2 = 0.0;
    unsigned int cv = 0, cb = 0;
#pragma unroll
    for (int k = 0; k < 4; k++) {
        bool valid = (tg[k] != 255);
        float nll = valid ? (__logf(s[k]) - xt[k]) : 0.f;
        v1 += (double)nll;
        cv += valid ? 1u : 0u;
        if (mm[k] & 1) {
            int v = g_parent[p0 + k];
            int p = v & IDXM;
            int vp = g_parent[p];
            while ((vp & IDXM) != p) { p = vp & IDXM; vp = g_parent[p]; }
            if (vp & FLAGB) { v2 += (double)nll; cb++; }
        }
    }

    const unsigned int full = 0xFFFFFFFFu;
#pragma unroll
    for (int o = 16; o > 0; o >>= 1) {
        v1 += __shfl_down_sync(full, v1, o);
        v2 += __shfl_down_sync(full, v2, o);
        cv += __shfl_down_sync(full, cv, o);
        cb += __shfl_down_sync(full, cb, o);
    }
    __shared__ double sh1[8], sh2[8];
    __shared__ unsigned int shc[8], shb[8];
    int lane = tid & 31, wid = tid >> 5;
    if (lane == 0) { sh1[wid] = v1; sh2[wid] = v2; shc[wid] = cv; shb[wid] = cb; }
    __syncthreads();
    if (wid == 0) {
        v1 = (lane < 8) ? sh1[lane] : 0.0;
        v2 = (lane < 8) ? sh2[lane] : 0.0;
        cv = (lane < 8) ? shc[lane] : 0u;
        cb = (lane < 8) ? shb[lane] : 0u;
#pragma unroll
        for (int o = 4; o > 0; o >>= 1) {
            v1 += __shfl_down_sync(full, v1, o);
            v2 += __shfl_down_sync(full, v2, o);
            cv += __shfl_down_sync(full, cv, o);
            cb += __shfl_down_sync(full, cb, o);
        }
        if (lane == 0) {
            atomicAdd(&g_sum_nll, v1);
            atomicAdd(&g_cnt_valid, (unsigned long long)cv);
            if (cb > 0 || v2 != 0.0) {
                atomicAdd(&g_sum_bnll, v2);
                atomicAdd(&g_cnt_b, (unsigned long long)cb);
            }
            __threadfence();
            unsigned int n = atomicAdd(&g_done, 1);
            if (n == (unsigned int)(NLL_GRID - 1)) {
                g_done = 0;   // reset for next graph replay
                unsigned long long tv = g_cnt_valid;
                unsigned long long tb = g_cnt_b;
                double ce = g_sum_nll / (double)(tv > 0 ? tv : 1ULL);
                double loss = ce;
                if (tb > 0) loss += 10.0 * (g_sum_bnll / (double)tb);
                out[0] = (float)loss;
            }
        }
    }
}

// ---------------- launch ---------------------------------------------------

extern "C" void kernel_launch(void* const* d_in, const int* in_sizes, int n_in,
                              void* d_out, int out_size) {
    const float* input  = (const float*)d_in[0];
    const int*   target = (const int*)d_in[1];
    float* out = (float*)d_out;

    k_canny<<<dim3(WW / TS, HH / TS, BB), 256>>>(target);
    k_seam<<<(NSEAM + 255) / 256, 256>>>();
    k_nllfused<<<NLL_GRID, 256>>>(input, target, out);
}

// round 16
// speedup vs baseline: 2.2751x; 2.2751x over previous
#include <cuda_runtime.h>

// Problem dims (fixed by the dataset)
#define BB 8
#define CC 19
#define HH 512
#define WW 1024
#define HWW (HH*WW)
#define NPIX (BB*HWW)

#define TS 32   // UF tile 32x32

// flag-in-parent encoding
#define FLAGB 0x40000000
#define IDXM  0x3FFFFFFF

// seam slot counts (horizontal vectorized 4 px/thread)
#define NSEAM_H4 (BB * 15 * WW / 4)     // 30720
#define NSEAM_V  (BB * 31 * HH)         // 126976
#define NSEAM_T  (NSEAM_H4 + NSEAM_V)

#define NLL_GRID (NPIX / 4 / 256)       // 4096 blocks

// ---------------- scratch (device globals; no allocation allowed) ----------
__device__ int            g_parent[NPIX];
__device__ unsigned char  g_wmask[NPIX];   // bit0=weak, bit1=strong
__device__ double         g_sum_nll;
__device__ double         g_sum_bnll;
__device__ unsigned long long g_cnt_valid;
__device__ unsigned long long g_cnt_b;
__device__ unsigned int   g_done = 0;

// ================= shared-memory union-find helpers ========================
__device__ __forceinline__ int find_s(int* sp, int x) {
    int p = sp[x];
    while (p != x) {
        int gp = sp[p];
        if (gp != p) sp[x] = gp;
        x = p; p = gp;
    }
    return x;
}

__device__ __forceinline__ void union_s(int* sp, int a, int b) {
    while (true) {
        a = find_s(sp, a);
        b = find_s(sp, b);
        if (a == b) return;
        if (a < b) { int t = a; a = b; b = t; }
        int old = atomicCAS(&sp[a], a, b);
        if (old == a) return;
        a = old;
    }
}

// ============ fused Sobel + NMS + threshold + tile-local UF + flags ========
// 32x32 tile, 256 threads, 4 px/thread; separable register-resident gradients
__global__ __launch_bounds__(256) void k_canny(const int* __restrict__ tgt) {
    __shared__ float simg[TS + 4][TS + 5];   // img halo 2, edge-clamped (+pad)
    __shared__ float smag[TS + 2][TS + 3];   // mag halo 1, 0 outside img (+pad)
    __shared__ int sp[TS * TS];
    __shared__ unsigned char lw[TS * TS];
    __shared__ unsigned char sfl[TS * TS];   // local root -> has strong member

    const int tid = threadIdx.x;
    const int b  = blockIdx.z;
    const int h0 = blockIdx.y * TS;
    const int w0 = blockIdx.x * TS;
    const int* timg = tgt + b * HWW;
    const int base = b * HWW;

    // zero the accumulators once (k_canny completes before any reader runs)
    if (blockIdx.x == 0 && blockIdx.y == 0 && blockIdx.z == 0 && tid == 0) {
        g_sum_nll = 0.0; g_sum_bnll = 0.0; g_cnt_valid = 0ULL; g_cnt_b = 0ULL;
    }

    // load image (target*255)%256, edge padded
    for (int l = tid; l < (TS + 4) * (TS + 4); l += 256) {
        int rr = l / (TS + 4), cc = l - rr * (TS + 4);
        int gh = min(max(h0 - 2 + rr, 0), HH - 1);
        int gw = min(max(w0 - 2 + cc, 0), WW - 1);
        int t = __ldg(timg + gh * WW + gw);
        simg[rr][cc] = (float)((t * 255) & 255);
    }
    __syncthreads();

    const int lr  = tid >> 3;         // center row 0..31 (tile-relative)
    const int lcb = (tid & 7) * 4;    // center col base 0,4,...,28

    float magk[4];
    unsigned char seck[4];

    // ---- center mags: separable 3x6 window, 18 LDS, all exact integers ----
    {
        float r0[6], r1[6], r2[6];
#pragma unroll
        for (int j = 0; j < 6; j++) {
            r0[j] = simg[lr + 1][lcb + 1 + j];
            r1[j] = simg[lr + 2][lcb + 1 + j];
            r2[j] = simg[lr + 3][lcb + 1 + j];
        }
        float v[6], d[6];
#pragma unroll
        for (int j = 0; j < 6; j++) {
            v[j] = r0[j] + 2.f * r1[j] + r2[j];   // vertical sum  (for gx)
            d[j] = r2[j] - r0[j];                 // vertical diff (for gy)
        }
#pragma unroll
        for (int k = 0; k < 4; k++) {
            float gx = v[k + 2] - v[k];
            float gy = d[k] + 2.f * d[k + 1] + d[k + 2];
            float ax = fabsf(gx), ay = fabsf(gy);
            float m = ax + ay;
            unsigned char sec;
            if (ay <= ax * 0.41421356f)      sec = 0;
            else if (ay >= ax * 2.41421356f) sec = 1;
            else sec = (gx * gy >= 0.f) ? 2 : 3;
            magk[k] = m;
            seck[k] = sec;
            smag[lr + 1][lcb + 1 + k] = m;
        }
    }

    // ---- halo ring of smag: 132 cells, generic 8-LDS formula --------------
    if (tid < 132) {
        int mr, mc;
        if (tid < 68) {                      // rows 0 and 33, cols 0..33
            mr = (tid < 34) ? 0 : 33;
            mc = (tid < 34) ? tid : tid - 34;
        } else {                             // cols 0 and 33, rows 1..32
            int t2 = tid - 68;
            mc = (t2 < 32) ? 0 : 33;
            mr = 1 + (t2 & 31);
        }
        int gh = h0 + mr - 1, gw = w0 + mc - 1;
        float m = 0.f;
        if (gh >= 0 && gh < HH && gw >= 0 && gw < WW) {
            float a00 = simg[mr][mc],     a01 = simg[mr][mc+1],     a02 = simg[mr][mc+2];
            float a10 = simg[mr+1][mc],                             a12 = simg[mr+1][mc+2];
            float a20 = simg[mr+2][mc],   a21 = simg[mr+2][mc+1],   a22 = simg[mr+2][mc+2];
            float gx = (a02 + 2.f*a12 + a22) - (a00 + 2.f*a10 + a20);
            float gy = (a20 + 2.f*a21 + a22) - (a00 + 2.f*a01 + a02);
            m = fabsf(gx) + fabsf(gy);
        }
        smag[mr][mc] = m;
    }
    __syncthreads();

    // ---- NMS (branchless neighbor addressing) + thresholds ----------------
    {
        int l0 = tid * 4;
        uchar4 mout;
        unsigned char* mo = (unsigned char*)&mout;
        int mr = lr + 1;
#pragma unroll
        for (int k = 0; k < 4; k++) {
            int mc = lcb + 1 + k;
            int sec = seck[k];
            int dr = (sec == 0) ? 0 : -1;
            int dc = (sec == 1) ? 0 : ((sec == 3) ? 1 : -1);
            float n1 = smag[mr + dr][mc + dc];
            float n2 = smag[mr - dr][mc - dc];
            float mag = magk[k];
            bool keep = (mag >= n1) && (mag > n2);
            unsigned char m = 0;
            if (keep && mag > 50.f)  m |= 1;
            if (keep && mag > 150.f) m |= 2;
            mo[k] = m;
            lw[l0 + k] = m;
            sp[l0 + k] = l0 + k;
            sfl[l0 + k] = 0;
        }
        int gidx = base + (h0 + lr) * WW + w0 + lcb;
        *(uchar4*)(g_wmask + gidx) = mout;
    }
    __syncthreads();

    // local UF over weak pixels
#pragma unroll
    for (int k = 0; k < 4; k++) {
        int l = tid * 4 + k;
        if (!(lw[l] & 1)) continue;
        int rr = l >> 5, cc = l & 31;
        if (cc > 0 && (lw[l - 1] & 1)) union_s(sp, l, l - 1);
        if (rr > 0) {
            if (lw[l - 32] & 1)              union_s(sp, l, l - 32);
            if (cc > 0  && (lw[l - 33] & 1)) union_s(sp, l, l - 33);
            if (cc < 31 && (lw[l - 31] & 1)) union_s(sp, l, l - 31);
        }
    }
    __syncthreads();

    // mark local roots of components containing a strong pixel
#pragma unroll
    for (int k = 0; k < 4; k++) {
        int l = tid * 4 + k;
        if (lw[l] & 2) sfl[find_s(sp, l)] = 1;
    }
    __syncthreads();

    // write global parents; root entries carry the strong-flag in bit 30
#pragma unroll
    for (int k = 0; k < 4; k++) {
        int l = tid * 4 + k;
        if (!(lw[l] & 1)) continue;
        int root = find_s(sp, l);
        int rr = l >> 5, cc = l & 31;
        int groot = base + (h0 + (root >> 5)) * WW + (w0 + (root & 31));
        int gi    = base + (h0 + rr) * WW + (w0 + cc);
        int val = (l == root && sfl[root]) ? (groot | FLAGB) : groot;
        g_parent[gi] = val;
    }
}

// ============ global union-find with flag propagation ======================
__device__ __forceinline__ int uf_find(int* P, int x) {
    int p = P[x] & IDXM;
    while (p != x) {
        int gp = P[p] & IDXM;
        if (gp != p) P[x] = gp;   // halving: x is non-root, pointer-only entry
        x = p; p = gp;
    }
    return x;
}

// plant the strong flag on the (current) root of x's component
__device__ __forceinline__ void uf_setflag(int* P, int x) {
    while (true) {
        int r = uf_find(P, x);
        int old = atomicOr(&P[r], FLAGB);
        if ((old & IDXM) == r) return;   // landed on a root: done
        x = old & IDXM;                  // r was re-linked concurrently: chase
    }
}

__device__ __forceinline__ void uf_union(int* P, int a, int b) {
    while (true) {
        a = uf_find(P, a);
        b = uf_find(P, b);
        if (a == b) return;
        if (a < b) { int t = a; a = b; b = t; }
        int aval = P[a];
        if ((aval & IDXM) != a) continue;        // stale root, retry
        int old = atomicCAS(&P[a], aval, b);     // full-word compare: flag-safe
        if (old == aval) {
            if (aval & FLAGB) uf_setflag(P, b);  // carry flag to the new root
            return;
        }
        // lost the race: retry from current roots
    }
}

// ====== seam-direct cross-tile unions ======================================
// horizontal: 4 px/thread, uchar4 early-out; vertical: scalar wi-fastest
__global__ __launch_bounds__(256) void k_seam() {
    int t = blockIdx.x * blockDim.x + threadIdx.x;
    if (t >= NSEAM_T) return;

    if (t < NSEAM_H4) {
        // horizontal seams: rows h = 32,64,...,480 (15/image), 4 px/thread
        int b  = t / (15 * (WW / 4));
        int r  = t - b * (15 * (WW / 4));
        int hi = r / (WW / 4);
        int w4 = (r - hi * (WW / 4)) * 4;
        int h  = (hi + 1) * TS;
        int base = b * HWW;
        int i0 = base + h * WW + w4;
        uchar4 cur = *(const uchar4*)(g_wmask + i0);
        unsigned int cw;
        memcpy(&cw, &cur, 4);
        if ((cw & 0x01010101u) == 0u) return;    // no weak px in this group
        unsigned char cm[4];
        memcpy(cm, &cur, 4);
        int rowup = base + (h - 1) * WW;
#pragma unroll
        for (int k = 0; k < 4; k++) {
            if (!(cm[k] & 1)) continue;
            int w = w4 + k;
            int i = i0 + k;
            if (g_wmask[rowup + w] & 1)                     uf_union(g_parent, i, rowup + w);
            if (w > 0      && (g_wmask[rowup + w - 1] & 1)) uf_union(g_parent, i, rowup + w - 1);
            if (w < WW - 1 && (g_wmask[rowup + w + 1] & 1)) uf_union(g_parent, i, rowup + w + 1);
        }
    } else {
        // vertical seams: cols w = 32,64,...,992 (31/image), wi FASTEST
        int t2 = t - NSEAM_H4;
        int wi = t2 % 31;
        int r  = t2 / 31;
        int h  = r % HH;
        int b  = r / HH;
        int w  = (wi + 1) * TS;
        int base = b * HWW;
        int i = base + h * WW + w;       // pixel with lc==0
        bool iw  = (g_wmask[i] & 1) != 0;
        bool lw_ = (g_wmask[i - 1] & 1) != 0;    // (h, w-1), lc==31
        if (iw && lw_) uf_union(g_parent, i, i - 1);
        // diagonals across the vertical seam (horizontal-seam rows covered above)
        if ((h & (TS - 1)) != 0) {
            int up = i - WW;
            if (iw  && (g_wmask[up - 1] & 1)) uf_union(g_parent, i, up - 1);
            if (lw_ && (g_wmask[up] & 1))     uf_union(g_parent, i - 1, up);
        }
    }
}

// ====== fused NLL + boundary reduce + final (chunked-5: best measured) =====
__global__ __launch_bounds__(256, 4) void k_nllfused(const float* __restrict__ in,
                                                     const int* __restrict__ tgt,
                                                     float* __restrict__ out) {
    const int tid = threadIdx.x;
    int p0 = (blockIdx.x * 256 + tid) * 4;
    int b = p0 / HWW;
    int off = p0 - b * HWW;
    const float* basep = in + (size_t)b * (CC * HWW) + off;

    int4 t4 = *(const int4*)(tgt + p0);
    int tg[4] = {t4.x, t4.y, t4.z, t4.w};

    float s[4]  = {0.f, 0.f, 0.f, 0.f};
    float xt[4] = {0.f, 0.f, 0.f, 0.f};

#pragma unroll 1
    for (int c0 = 0; c0 < CC; c0 += 5) {
        const int CN = (CC - c0 < 5) ? (CC - c0) : 5;
        float f[5][4];
#pragma unroll
        for (int j = 0; j < 5; j++) {
            if (j < CN) {
                float4 v = __ldg((const float4*)(basep + (size_t)(c0 + j) * HWW));
                f[j][0] = v.x; f[j][1] = v.y; f[j][2] = v.z; f[j][3] = v.w;
            }
        }
#pragma unroll
        for (int j = 0; j < 5; j++) {
            if (j < CN) {
#pragma unroll
                for (int k = 0; k < 4; k++) {
                    s[k] += __expf(f[j][k]);
                    if (c0 + j == tg[k]) xt[k] = f[j][k];
                }
            }
        }
    }

    uchar4 m4 = *(const uchar4*)(g_wmask + p0);
    unsigned char mm[4] = {m4.x, m4.y, m4.z, m4.w};

    double v1 = 0.0, v2 = 0.0;
    unsigned int cv = 0, cb = 0;
#pragma unroll
    for (int k = 0; k < 4; k++) {
        bool valid = (tg[k] != 255);
        float nll = valid ? (__logf(s[k]) - xt[k]) : 0.f;
        v1 += (double)nll;
        cv += valid ? 1u : 0u;
        if (mm[k] & 1) {
            // read-only root chase; flag rides in the root's parent word
            int v = g_parent[p0 + k];
            int p = v & IDXM;
            int vp = g_parent[p];
            while ((vp & IDXM) != p) { p = vp & IDXM; vp = g_parent[p]; }
            if (vp & FLAGB) { v2 += (double)nll; cb++; }
        }
    }

    const unsigned int full = 0xFFFFFFFFu;
#pragma unroll
    for (int o = 16; o > 0; o >>= 1) {
        v1 += __shfl_down_sync(full, v1, o);
        v2 += __shfl_down_sync(full, v2, o);
        cv += __shfl_down_sync(full, cv, o);
        cb += __shfl_down_sync(full, cb, o);
    }
    __shared__ double sh1[8], sh2[8];
    __shared__ unsigned int shc[8], shb[8];
    int lane = tid & 31, wid = tid >> 5;
    if (lane == 0) { sh1[wid] = v1; sh2[wid] = v2; shc[wid] = cv; shb[wid] = cb; }
    __syncthreads();
    if (wid == 0) {
        v1 = (lane < 8) ? sh1[lane] : 0.0;
        v2 = (lane < 8) ? sh2[lane] : 0.0;
        cv = (lane < 8) ? shc[lane] : 0u;
        cb = (lane < 8) ? shb[lane] : 0u;
#pragma unroll
        for (int o = 4; o > 0; o >>= 1) {
            v1 += __shfl_down_sync(full, v1, o);
            v2 += __shfl_down_sync(full, v2, o);
            cv += __shfl_down_sync(full, cv, o);
            cb += __shfl_down_sync(full, cb, o);
        }
        if (lane == 0) {
            atomicAdd(&g_sum_nll, v1);
            atomicAdd(&g_cnt_valid, (unsigned long long)cv);
            if (cb > 0 || v2 != 0.0) {
                atomicAdd(&g_sum_bnll, v2);
                atomicAdd(&g_cnt_b, (unsigned long long)cb);
            }
            // last-block-done: finisher writes the loss (saves a launch)
            __threadfence();
            unsigned int n = atomicAdd(&g_done, 1);
            if (n == (unsigned int)(NLL_GRID - 1)) {
                g_done = 0;   // reset for next graph replay
                unsigned long long tv = g_cnt_valid;
                unsigned long long tb = g_cnt_b;
                double ce = g_sum_nll / (double)(tv > 0 ? tv : 1ULL);
                double loss = ce;
                if (tb > 0) loss += 10.0 * (g_sum_bnll / (double)tb);
                out[0] = (float)loss;
            }
        }
    }
}

// ---------------- launch ---------------------------------------------------

extern "C" void kernel_launch(void* const* d_in, const int* in_sizes, int n_in,
                              void* d_out, int out_size) {
    const float* input  = (const float*)d_in[0];
    const int*   target = (const int*)d_in[1];
    float* out = (float*)d_out;

    k_canny<<<dim3(WW / TS, HH / TS, BB), 256>>>(target);
    k_seam<<<(NSEAM_T + 255) / 256, 256>>>();
    k_nllfused<<<NLL_GRID, 256>>>(input, target, out);
}

// round 17
// speedup vs baseline: 2.5987x; 1.1422x over previous
#include <cuda_runtime.h>

// Problem dims (fixed by the dataset)
#define BB 8
#define CC 19
#define HH 512
#define WW 1024
#define HWW (HH*WW)
#define NPIX (BB*HWW)

#define TS 32   // UF tile 32x32

// flag-in-parent encoding
#define FLAGB 0x40000000
#define IDXM  0x3FFFFFFF

// seam slot counts (scalar, proven form)
#define NSEAM_H (BB * 15 * WW)          // 15 interior seam rows per image
#define NSEAM_V (BB * 31 * HH)          // 31 interior seam cols per image
#define NSEAM   (NSEAM_H + NSEAM_V)

#define NLL_GRID (NPIX / 4 / 256)       // 4096 blocks

// ---------------- scratch (device globals; no allocation allowed) ----------
__device__ int            g_parent[NPIX];
__device__ unsigned char  g_wmask[NPIX];   // bit0=weak, bit1=strong
__device__ double         g_sum_nll;
__device__ double         g_sum_bnll;
__device__ unsigned long long g_cnt_valid;
__device__ unsigned long long g_cnt_b;
__device__ unsigned int   g_done = 0;

// ================= shared-memory union-find helpers ========================
__device__ __forceinline__ int find_s(int* sp, int x) {
    int p = sp[x];
    while (p != x) {
        int gp = sp[p];
        if (gp != p) sp[x] = gp;
        x = p; p = gp;
    }
    return x;
}

__device__ __forceinline__ void union_s(int* sp, int a, int b) {
    while (true) {
        a = find_s(sp, a);
        b = find_s(sp, b);
        if (a == b) return;
        if (a < b) { int t = a; a = b; b = t; }
        int old = atomicCAS(&sp[a], a, b);
        if (old == a) return;
        a = old;
    }
}

// ============ fused Sobel + NMS + threshold + tile-local UF + flags ========
// 32x32 tile, 256 threads, 4 px/thread; separable register-resident gradients
__global__ __launch_bounds__(256) void k_canny(const int* __restrict__ tgt) {
    __shared__ float simg[TS + 4][TS + 5];   // img halo 2, edge-clamped (+pad)
    __shared__ float smag[TS + 2][TS + 3];   // mag halo 1, 0 outside img (+pad)
    __shared__ int sp[TS * TS];
    __shared__ unsigned char lw[TS * TS];
    __shared__ unsigned char sfl[TS * TS];   // local root -> has strong member

    const int tid = threadIdx.x;
    const int b  = blockIdx.z;
    const int h0 = blockIdx.y * TS;
    const int w0 = blockIdx.x * TS;
    const int* timg = tgt + b * HWW;
    const int base = b * HWW;

    // zero the accumulators once (k_canny completes before any reader runs)
    if (blockIdx.x == 0 && blockIdx.y == 0 && blockIdx.z == 0 && tid == 0) {
        g_sum_nll = 0.0; g_sum_bnll = 0.0; g_cnt_valid = 0ULL; g_cnt_b = 0ULL;
    }

    // load image (target*255)%256, edge padded
    for (int l = tid; l < (TS + 4) * (TS + 4); l += 256) {
        int rr = l / (TS + 4), cc = l - rr * (TS + 4);
        int gh = min(max(h0 - 2 + rr, 0), HH - 1);
        int gw = min(max(w0 - 2 + cc, 0), WW - 1);
        int t = __ldg(timg + gh * WW + gw);
        simg[rr][cc] = (float)((t * 255) & 255);
    }
    __syncthreads();

    const int lr  = tid >> 3;         // center row 0..31 (tile-relative)
    const int lcb = (tid & 7) * 4;    // center col base 0,4,...,28

    float magk[4];
    unsigned char seck[4];

    // ---- center mags: separable 3x6 window, 18 LDS, all exact integers ----
    {
        float r0[6], r1[6], r2[6];
#pragma unroll
        for (int j = 0; j < 6; j++) {
            r0[j] = simg[lr + 1][lcb + 1 + j];
            r1[j] = simg[lr + 2][lcb + 1 + j];
            r2[j] = simg[lr + 3][lcb + 1 + j];
        }
        float v[6], d[6];
#pragma unroll
        for (int j = 0; j < 6; j++) {
            v[j] = r0[j] + 2.f * r1[j] + r2[j];   // vertical sum  (for gx)
            d[j] = r2[j] - r0[j];                 // vertical diff (for gy)
        }
#pragma unroll
        for (int k = 0; k < 4; k++) {
            float gx = v[k + 2] - v[k];
            float gy = d[k] + 2.f * d[k + 1] + d[k + 2];
            float ax = fabsf(gx), ay = fabsf(gy);
            float m = ax + ay;
            unsigned char sec;
            if (ay <= ax * 0.41421356f)      sec = 0;
            else if (ay >= ax * 2.41421356f) sec = 1;
            else sec = (gx * gy >= 0.f) ? 2 : 3;
            magk[k] = m;
            seck[k] = sec;
            smag[lr + 1][lcb + 1 + k] = m;
        }
    }

    // ---- halo ring of smag: 132 cells, generic 8-LDS formula --------------
    if (tid < 132) {
        int mr, mc;
        if (tid < 68) {                      // rows 0 and 33, cols 0..33
            mr = (tid < 34) ? 0 : 33;
            mc = (tid < 34) ? tid : tid - 34;
        } else {                             // cols 0 and 33, rows 1..32
            int t2 = tid - 68;
            mc = (t2 < 32) ? 0 : 33;
            mr = 1 + (t2 & 31);
        }
        int gh = h0 + mr - 1, gw = w0 + mc - 1;
        float m = 0.f;
        if (gh >= 0 && gh < HH && gw >= 0 && gw < WW) {
            float a00 = simg[mr][mc],     a01 = simg[mr][mc+1],     a02 = simg[mr][mc+2];
            float a10 = simg[mr+1][mc],                             a12 = simg[mr+1][mc+2];
            float a20 = simg[mr+2][mc],   a21 = simg[mr+2][mc+1],   a22 = simg[mr+2][mc+2];
            float gx = (a02 + 2.f*a12 + a22) - (a00 + 2.f*a10 + a20);
            float gy = (a20 + 2.f*a21 + a22) - (a00 + 2.f*a01 + a02);
            m = fabsf(gx) + fabsf(gy);
        }
        smag[mr][mc] = m;
    }
    __syncthreads();

    // ---- NMS (branchless neighbor addressing) + thresholds ----------------
    {
        int l0 = tid * 4;
        uchar4 mout;
        unsigned char* mo = (unsigned char*)&mout;
        int mr = lr + 1;
#pragma unroll
        for (int k = 0; k < 4; k++) {
            int mc = lcb + 1 + k;
            int sec = seck[k];
            int dr = (sec == 0) ? 0 : -1;
            int dc = (sec == 1) ? 0 : ((sec == 3) ? 1 : -1);
            float n1 = smag[mr + dr][mc + dc];
            float n2 = smag[mr - dr][mc - dc];
            float mag = magk[k];
            bool keep = (mag >= n1) && (mag > n2);
            unsigned char m = 0;
            if (keep && mag > 50.f)  m |= 1;
            if (keep && mag > 150.f) m |= 2;
            mo[k] = m;
            lw[l0 + k] = m;
            sp[l0 + k] = l0 + k;
            sfl[l0 + k] = 0;
        }
        int gidx = base + (h0 + lr) * WW + w0 + lcb;
        *(uchar4*)(g_wmask + gidx) = mout;
    }
    __syncthreads();

    // local UF over weak pixels
#pragma unroll
    for (int k = 0; k < 4; k++) {
        int l = tid * 4 + k;
        if (!(lw[l] & 1)) continue;
        int rr = l >> 5, cc = l & 31;
        if (cc > 0 && (lw[l - 1] & 1)) union_s(sp, l, l - 1);
        if (rr > 0) {
            if (lw[l - 32] & 1)              union_s(sp, l, l - 32);
            if (cc > 0  && (lw[l - 33] & 1)) union_s(sp, l, l - 33);
            if (cc < 31 && (lw[l - 31] & 1)) union_s(sp, l, l - 31);
        }
    }
    __syncthreads();

    // mark local roots of components containing a strong pixel
#pragma unroll
    for (int k = 0; k < 4; k++) {
        int l = tid * 4 + k;
        if (lw[l] & 2) sfl[find_s(sp, l)] = 1;
    }
    __syncthreads();

    // write global parents; root entries carry the strong-flag in bit 30
#pragma unroll
    for (int k = 0; k < 4; k++) {
        int l = tid * 4 + k;
        if (!(lw[l] & 1)) continue;
        int root = find_s(sp, l);
        int rr = l >> 5, cc = l & 31;
        int groot = base + (h0 + (root >> 5)) * WW + (w0 + (root & 31));
        int gi    = base + (h0 + rr) * WW + (w0 + cc);
        int val = (l == root && sfl[root]) ? (groot | FLAGB) : groot;
        g_parent[gi] = val;
    }
}

// ============ global union-find with flag propagation ======================
__device__ __forceinline__ int uf_find(int* P, int x) {
    int p = P[x] & IDXM;
    while (p != x) {
        int gp = P[p] & IDXM;
        if (gp != p) P[x] = gp;   // halving: x is non-root, pointer-only entry
        x = p; p = gp;
    }
    return x;
}

// plant the strong flag on the (current) root of x's component
__device__ __forceinline__ void uf_setflag(int* P, int x) {
    while (true) {
        int r = uf_find(P, x);
        int old = atomicOr(&P[r], FLAGB);
        if ((old & IDXM) == r) return;   // landed on a root: done
        x = old & IDXM;                  // r was re-linked concurrently: chase
    }
}

__device__ __forceinline__ void uf_union(int* P, int a, int b) {
    while (true) {
        a = uf_find(P, a);
        b = uf_find(P, b);
        if (a == b) return;
        if (a < b) { int t = a; a = b; b = t; }
        int aval = P[a];
        if ((aval & IDXM) != a) continue;        // stale root, retry
        int old = atomicCAS(&P[a], aval, b);     // full-word compare: flag-safe
        if (old == aval) {
            if (aval & FLAGB) uf_setflag(P, b);  // carry flag to the new root
            return;
        }
        // lost the race: retry from current roots
    }
}

// ====== seam-direct cross-tile unions: one thread per seam pixel slot ======
// (scalar form — measured best across R9/R13/R14)
__global__ __launch_bounds__(256) void k_seam() {
    int t = blockIdx.x * blockDim.x + threadIdx.x;
    if (t >= NSEAM) return;

    if (t < NSEAM_H) {
        // horizontal seams: rows h = 32,64,...,480 (15 per image), w fastest
        int b  = t / (15 * WW);
        int r  = t - b * (15 * WW);
        int hi = r / WW;
        int w  = r - hi * WW;
        int h  = (hi + 1) * TS;
        int base = b * HWW;
        int i = base + h * WW + w;
        if (!(g_wmask[i] & 1)) return;
        int rowup = base + (h - 1) * WW;
        if (g_wmask[rowup + w] & 1)                     uf_union(g_parent, i, rowup + w);
        if (w > 0      && (g_wmask[rowup + w - 1] & 1)) uf_union(g_parent, i, rowup + w - 1);
        if (w < WW - 1 && (g_wmask[rowup + w + 1] & 1)) uf_union(g_parent, i, rowup + w + 1);
    } else {
        // vertical seams: cols w = 32,64,...,992 (31 per image), wi FASTEST
        int t2 = t - NSEAM_H;
        int wi = t2 % 31;
        int r  = t2 / 31;
        int h  = r % HH;
        int b  = r / HH;
        int w  = (wi + 1) * TS;
        int base = b * HWW;
        int i = base + h * WW + w;       // pixel with lc==0
        bool iw  = (g_wmask[i] & 1) != 0;
        bool lw_ = (g_wmask[i - 1] & 1) != 0;    // (h, w-1), lc==31
        if (iw && lw_) uf_union(g_parent, i, i - 1);
        // diagonals across the vertical seam (horizontal-seam rows covered above)
        if ((h & (TS - 1)) != 0) {
            int up = i - WW;
            if (iw  && (g_wmask[up - 1] & 1)) uf_union(g_parent, i, up - 1);
            if (lw_ && (g_wmask[up] & 1))     uf_union(g_parent, i - 1, up);
        }
    }
}

// ====== fused NLL + boundary reduce + final ================================
// chunked-5 loads with per-block channel-phase rotation (anti-aliasing)
__global__ __launch_bounds__(256, 4) void k_nllfused(const float* __restrict__ in,
                                                     const int* __restrict__ tgt,
                                                     float* __restrict__ out) {
    const int tid = threadIdx.x;
    int p0 = (blockIdx.x * 256 + tid) * 4;
    int b = p0 / HWW;
    int off = p0 - b * HWW;
    const float* basep = in + (size_t)b * (CC * HWW) + off;

    int4 t4 = *(const int4*)(tgt + p0);
    int tg[4] = {t4.x, t4.y, t4.z, t4.w};

    float s[4]  = {0.f, 0.f, 0.f, 0.f};
    float xt[4] = {0.f, 0.f, 0.f, 0.f};

    const int rot = blockIdx.x & 3;   // rotate chunk order per block

#pragma unroll 1
    for (int q = 0; q < 4; q++) {
        const int ci = (q + rot) & 3;          // chunk index 0..3
        const int c0 = ci * 5;                 // chunk channels c0..c0+CN-1
        const int CN = (ci == 3) ? 4 : 5;      // 5,5,5,4 covers 19 channels
        float f[5][4];
#pragma unroll
        for (int j = 0; j < 5; j++) {
            if (j < CN) {
                float4 v = __ldg((const float4*)(basep + (size_t)(c0 + j) * HWW));
                f[j][0] = v.x; f[j][1] = v.y; f[j][2] = v.z; f[j][3] = v.w;
            }
        }
#pragma unroll
        for (int j = 0; j < 5; j++) {
            if (j < CN) {
#pragma unroll
                for (int k = 0; k < 4; k++) {
                    s[k] += __expf(f[j][k]);
                    if (c0 + j == tg[k]) xt[k] = f[j][k];
                }
            }
        }
    }

    uchar4 m4 = *(const uchar4*)(g_wmask + p0);
    unsigned char mm[4] = {m4.x, m4.y, m4.z, m4.w};

    double v1 = 0.0, v2 = 0.0;
    unsigned int cv = 0, cb = 0;
#pragma unroll
    for (int k = 0; k < 4; k++) {
        bool valid = (tg[k] != 255);
        float nll = valid ? (__logf(s[k]) - xt[k]) : 0.f;
        v1 += (double)nll;
        cv += valid ? 1u : 0u;
        if (mm[k] & 1) {
            // read-only root chase; flag rides in the root's parent word
            int v = g_parent[p0 + k];
            int p = v & IDXM;
            int vp = g_parent[p];
            while ((vp & IDXM) != p) { p = vp & IDXM; vp = g_parent[p]; }
            if (vp & FLAGB) { v2 += (double)nll; cb++; }
        }
    }

    const unsigned int full = 0xFFFFFFFFu;
#pragma unroll
    for (int o = 16; o > 0; o >>= 1) {
        v1 += __shfl_down_sync(full, v1, o);
        v2 += __shfl_down_sync(full, v2, o);
        cv += __shfl_down_sync(full, cv, o);
        cb += __shfl_down_sync(full, cb, o);
    }
    __shared__ double sh1[8], sh2[8];
    __shared__ unsigned int shc[8], shb[8];
    int lane = tid & 31, wid = tid >> 5;
    if (lane == 0) { sh1[wid] = v1; sh2[wid] = v2; shc[wid] = cv; shb[wid] = cb; }
    __syncthreads();
    if (wid == 0) {
        v1 = (lane < 8) ? sh1[lane] : 0.0;
        v2 = (lane < 8) ? sh2[lane] : 0.0;
        cv = (lane < 8) ? shc[lane] : 0u;
        cb = (lane < 8) ? shb[lane] : 0u;
#pragma unroll
        for (int o = 4; o > 0; o >>= 1) {
            v1 += __shfl_down_sync(full, v1, o);
            v2 += __shfl_down_sync(full, v2, o);
            cv += __shfl_down_sync(full, cv, o);
            cb += __shfl_down_sync(full, cb, o);
        }
        if (lane == 0) {
            atomicAdd(&g_sum_nll, v1);
            atomicAdd(&g_cnt_valid, (unsigned long long)cv);
            if (cb > 0 || v2 != 0.0) {
                atomicAdd(&g_sum_bnll, v2);
                atomicAdd(&g_cnt_b, (unsigned long long)cb);
            }
            // last-block-done: finisher writes the loss (saves a launch)
            __threadfence();
            unsigned int n = atomicAdd(&g_done, 1);
            if (n == (unsigned int)(NLL_GRID - 1)) {
                g_done = 0;   // reset for next graph replay
                unsigned long long tv = g_cnt_valid;
                unsigned long long tb = g_cnt_b;
                double ce = g_sum_nll / (double)(tv > 0 ? tv : 1ULL);
                double loss = ce;
                if (tb > 0) loss += 10.0 * (g_sum_bnll / (double)tb);
                out[0] = (float)loss;
            }
        }
    }
}

// ---------------- launch ---------------------------------------------------

extern "C" void kernel_launch(void* const* d_in, const int* in_sizes, int n_in,
                              void* d_out, int out_size) {
    const float* input  = (const float*)d_in[0];
    const int*   target = (const int*)d_in[1];
    float* out = (float*)d_out;

    k_canny<<<dim3(WW / TS, HH / TS, BB), 256>>>(target);
    k_seam<<<(NSEAM + 255) / 256, 256>>>();
    k_nllfused<<<NLL_GRID, 256>>>(input, target, out);
}